// round 6
// baseline (speedup 1.0000x reference)
#include <cuda_runtime.h>
#include <cuda_bf16.h>

// Embedding gather: out[n, :] = embeddings[inputs[n], :]
// N = 16384 rows, EMB = 128 floats = 32 float4 per row. Flat: 524288 float4.
// Config: 512 blocks x 512 threads, U=2 per thread.
//   - identical per-thread work to the best config (R4), but half the CTA
//     dispatch count; still a single wave (4 blocks/SM = 64 warps/SM).

#define N_ROWS    16384
#define EMB_F4    32                          // float4 per row
#define TOTAL_F4  (N_ROWS * EMB_F4)           // 524288
#define THREADS   512
#define U         2
#define NTHREADS_TOTAL (TOTAL_F4 / U)         // 262144
#define NBLOCKS   (NTHREADS_TOTAL / THREADS)  // 512

__global__ __launch_bounds__(THREADS)
void onehot_embed_gather_b512(const int* __restrict__ idx,
                              const float4* __restrict__ emb,   // [VOCAB, 32]
                              float4* __restrict__ out)          // [N, 32]
{
    const int tid = blockIdx.x * THREADS + threadIdx.x;

    // Batched independent index loads (warp-uniform broadcast, 1 sector each).
    int e[U];
    #pragma unroll
    for (int u = 0; u < U; u++) {
        const int pos = tid + u * NTHREADS_TOTAL;
        e[u] = __ldg(&idx[pos >> 5]);
    }

    // Batched independent 16B gather loads.
    float4 v[U];
    #pragma unroll
    for (int u = 0; u < U; u++) {
        const int pos  = tid + u * NTHREADS_TOTAL;
        const int lane = pos & (EMB_F4 - 1);
        v[u] = __ldg(&emb[(long long)e[u] * EMB_F4 + lane]);
    }

    // Coalesced stores.
    #pragma unroll
    for (int u = 0; u < U; u++) {
        const int pos = tid + u * NTHREADS_TOTAL;
        out[pos] = v[u];
    }
}

extern "C" void kernel_launch(void* const* d_in, const int* in_sizes, int n_in,
                              void* d_out, int out_size)
{
    const int*    idx = (const int*)   d_in[0];   // int32 [16384]
    const float4* emb = (const float4*)d_in[1];   // float32 [32000,128]
    float4*       out = (float4*)      d_out;     // float32 [16384,128]

    onehot_embed_gather_b512<<<NBLOCKS, THREADS>>>(idx, emb, out);
}

// round 7
// speedup vs baseline: 1.0435x; 1.0435x over previous
#include <cuda_runtime.h>
#include <cuda_bf16.h>

// Embedding gather: out[n, :] = embeddings[inputs[n], :]
// N = 16384 rows, EMB = 128 floats = 32 float4 per row. Flat: 524288 float4.
//
// Final config (best of 5 measured): 1024 blocks x 256 threads, U=2.
//   - single wave, ~7 blocks/SM, oe*MLP_p1 under the L1tex-queue spread threshold
//   - 2 independent gathers per thread; idx loads are warp-uniform broadcasts
//   - kernel is launch/drain-floor bound (~5 of ~6 us fixed); all pipes <16%

#define N_ROWS    16384
#define EMB_F4    32                          // float4 per row
#define TOTAL_F4  (N_ROWS * EMB_F4)           // 524288
#define THREADS   256
#define U         2
#define NTHREADS_TOTAL (TOTAL_F4 / U)         // 262144
#define NBLOCKS   (NTHREADS_TOTAL / THREADS)  // 1024

__global__ __launch_bounds__(THREADS)
void onehot_embed_gather_final(const int* __restrict__ idx,
                               const float4* __restrict__ emb,   // [VOCAB, 32]
                               float4* __restrict__ out)          // [N, 32]
{
    const int tid = blockIdx.x * THREADS + threadIdx.x;

    // Batched independent index loads (warp-uniform broadcast, 1 sector each).
    int e[U];
    #pragma unroll
    for (int u = 0; u < U; u++) {
        const int pos = tid + u * NTHREADS_TOTAL;
        e[u] = __ldg(&idx[pos >> 5]);
    }

    // Batched independent 16B gather loads.
    float4 v[U];
    #pragma unroll
    for (int u = 0; u < U; u++) {
        const int pos  = tid + u * NTHREADS_TOTAL;
        const int lane = pos & (EMB_F4 - 1);
        v[u] = __ldg(&emb[(long long)e[u] * EMB_F4 + lane]);
    }

    // Coalesced stores.
    #pragma unroll
    for (int u = 0; u < U; u++) {
        const int pos = tid + u * NTHREADS_TOTAL;
        out[pos] = v[u];
    }
}

extern "C" void kernel_launch(void* const* d_in, const int* in_sizes, int n_in,
                              void* d_out, int out_size)
{
    const int*    idx = (const int*)   d_in[0];   // int32 [16384]
    const float4* emb = (const float4*)d_in[1];   // float32 [32000,128]
    float4*       out = (float4*)      d_out;     // float32 [16384,128]

    onehot_embed_gather_final<<<NBLOCKS, THREADS>>>(idx, emb, out);
}